// round 4
// baseline (speedup 1.0000x reference)
#include <cuda_runtime.h>
#include <math.h>

#define B_ 8
#define S_ 1024
#define D_ 512
#define H_ 8
#define DK_ 64

#define TM 32
#define BJ 256
#define SS_STRIDE 1032
#define SQ_STRIDE 68
#define SV_STRIDE 68

typedef unsigned long long ull;

__device__ __forceinline__ void fma2(ull &d, ull a, ull b){
    asm("fma.rn.f32x2 %0, %1, %2, %0;" : "+l"(d) : "l"(a), "l"(b));
}
__device__ __forceinline__ ull pack2(float lo, float hi){
    ull d; asm("mov.b64 %0, {%1, %2};" : "=l"(d) : "f"(lo), "f"(hi)); return d;
}
__device__ __forceinline__ float2 unpack2(ull v){
    float2 f; asm("mov.b64 {%0, %1}, %2;" : "=f"(f.x), "=f"(f.y) : "l"(v)); return f;
}

// scratch (device globals; no allocation allowed)
__device__ float g_qk[B_*H_*S_*DK_];   // 16 MB, q == k (kq_same)
__device__ float g_v [B_*H_*S_*DK_];   // 16 MB
__device__ float g_attn[B_*S_*D_];     // 16 MB

// ---------------------------------------------------------------------------
// 128(M) x 64(N) fp32 GEMM, f32x2 FMA, pairs along M:  dst = A @ W^T + bias
// acc[mp][n] holds rows (2mp, 2mp+1) of column n.  Only B is duplicated in
// smem; A pairs come free from [kk][m] layout.  16 ull accs -> low regs.
// ---------------------------------------------------------------------------
__global__ __launch_bounds__(256, 3) void gemm128(
    const float* __restrict__ A, const float* __restrict__ W,
    const float* __restrict__ bias, float* __restrict__ dst, int head_split)
{
    __shared__ float sA [16*136];   // [kk][m]   m=0..127
    __shared__ float sBd[16*136];   // [kk][2n]  n=0..63 duplicated

    const int m0 = blockIdx.y*128, n0 = blockIdx.x*64;
    const int tid = threadIdx.x;
    const int tx = tid & 15;        // 16 n-groups * 4
    const int ty = tid >> 4;        // 16 m-groups * 8
    const int lrow = tid >> 1;      // 0..127 (A load row)
    const int lk   = (tid & 1)*8;   // A k-offset
    const int wrow = tid >> 2;      // 0..63 (W load row)
    const int wk   = (tid & 3)*4;   // W k-offset

    ull acc[4][4];
    #pragma unroll
    for (int mp=0; mp<4; ++mp)
        #pragma unroll
        for (int n=0; n<4; ++n) acc[mp][n]=0ULL;

    for (int k0=0; k0<D_; k0+=16){
        float4 a0 = *(const float4*)(A + (long)(m0+lrow)*D_ + k0+lk);
        float4 a1 = *(const float4*)(A + (long)(m0+lrow)*D_ + k0+lk+4);
        float4 bw = *(const float4*)(W + (long)(n0+wrow)*D_ + k0+wk);
        __syncthreads();
        sA[(lk+0)*136 + lrow] = a0.x;
        sA[(lk+1)*136 + lrow] = a0.y;
        sA[(lk+2)*136 + lrow] = a0.z;
        sA[(lk+3)*136 + lrow] = a0.w;
        sA[(lk+4)*136 + lrow] = a1.x;
        sA[(lk+5)*136 + lrow] = a1.y;
        sA[(lk+6)*136 + lrow] = a1.z;
        sA[(lk+7)*136 + lrow] = a1.w;
        *(ull*)(sBd + (wk+0)*136 + 2*wrow) = pack2(bw.x, bw.x);
        *(ull*)(sBd + (wk+1)*136 + 2*wrow) = pack2(bw.y, bw.y);
        *(ull*)(sBd + (wk+2)*136 + 2*wrow) = pack2(bw.z, bw.z);
        *(ull*)(sBd + (wk+3)*136 + 2*wrow) = pack2(bw.w, bw.w);
        __syncthreads();
        #pragma unroll
        for (int kk=0; kk<16; ++kk){
            const float* ap = sA  + kk*136 + ty*8;
            const float* bp = sBd + kk*136 + tx*8;
            ulonglong2 a01 = *(const ulonglong2*)(ap);
            ulonglong2 a23 = *(const ulonglong2*)(ap+4);
            ulonglong2 b01 = *(const ulonglong2*)(bp);
            ulonglong2 b23 = *(const ulonglong2*)(bp+4);
            #define GROW(mp, apair) \
                fma2(acc[mp][0], apair, b01.x); fma2(acc[mp][1], apair, b01.y); \
                fma2(acc[mp][2], apair, b23.x); fma2(acc[mp][3], apair, b23.y);
            GROW(0, a01.x) GROW(1, a01.y) GROW(2, a23.x) GROW(3, a23.y)
            #undef GROW
        }
    }

    const int n = n0 + tx*4;
    float4 bi = *(const float4*)(bias + n);
    #pragma unroll
    for (int mp=0; mp<4; ++mp){
        float2 u0 = unpack2(acc[mp][0]);
        float2 u1 = unpack2(acc[mp][1]);
        float2 u2 = unpack2(acc[mp][2]);
        float2 u3 = unpack2(acc[mp][3]);
        float4 v0; v0.x=u0.x+bi.x; v0.y=u1.x+bi.y; v0.z=u2.x+bi.z; v0.w=u3.x+bi.w;
        float4 v1; v1.x=u0.y+bi.x; v1.y=u1.y+bi.y; v1.z=u2.y+bi.z; v1.w=u3.y+bi.w;
        int r0 = m0 + ty*8 + 2*mp;
        if (head_split){
            int hh = n >> 6, dd = n & 63;
            int bb0 = r0 >> 10, ss0 = r0 & 1023;
            int bb1 = (r0+1) >> 10, ss1 = (r0+1) & 1023;
            *(float4*)(dst + (((long)bb0*H_ + hh)*S_ + ss0)*DK_ + dd) = v0;
            *(float4*)(dst + (((long)bb1*H_ + hh)*S_ + ss1)*DK_ + dd) = v1;
        } else {
            *(float4*)(dst + (long)r0*D_ + n) = v0;
            *(float4*)(dst + (long)(r0+1)*D_ + n) = v1;
        }
    }
}

// ---------------------------------------------------------------------------
// Attention with distance decay.  One block = 32 query rows of one (b,h),
// 512 threads.  Scores in SMEM (32 x 1024); K and V kept row-major.
// ---------------------------------------------------------------------------
__global__ __launch_bounds__(512) void attn_kernel(
    const float* __restrict__ utT, const float* __restrict__ gammas)
{
    extern __shared__ float smem[];
    float* sS   = smem;                       // 32*1032
    float* sQ   = sS  + TM*SS_STRIDE;         // 32*68
    float* sKV  = sQ  + TM*SQ_STRIDE;         // 256*68 (K or V tile, row-major)
    float* sInv = sKV + BJ*SV_STRIDE;         // 32

    const int i0 = blockIdx.x * TM;
    const int h  = blockIdx.y;
    const int b  = blockIdx.z;
    const int tid = threadIdx.x;
    const long bh = (long)(b*H_ + h);
    const float* Kbase = g_qk + bh*(long)(S_*DK_);
    const float* Vbase = g_v  + bh*(long)(S_*DK_);
    const int TJn  = (i0 + TM + BJ - 1) / BJ;
    const int JMAX = TJn * BJ;

    // ---- load Q tile (32 x 64): one float4 per thread ----
    {
        int row = tid >> 4, c4 = (tid & 15)*4;
        float4 v = *(const float4*)(Kbase + (long)(i0+row)*DK_ + c4);
        *(float4*)(sQ + row*SQ_STRIDE + c4) = v;
    }

    // ---- score GEMM: sS[i][j] = (q_i . k_j)/8 * utT[b,i,j] ----
    const int tx = tid & 63;
    const int ty = tid >> 6;
    const float kscale = 0.125f;

    for (int jt=0; jt<TJn; ++jt){
        const int j0 = jt*BJ;
        __syncthreads();
        #pragma unroll
        for (int it=0; it<8; ++it){
            int idx = tid + it*512;
            int row = idx >> 4, c4 = (idx & 15)*4;
            float4 v = *(const float4*)(Kbase + (long)(j0+row)*DK_ + c4);
            *(float4*)(sKV + row*SV_STRIDE + c4) = v;
        }
        __syncthreads();

        float acc[4][4] = {};
        #pragma unroll 2
        for (int kk=0; kk<DK_; ++kk){
            float k0v = sKV[(tx*4+0)*SV_STRIDE + kk];
            float k1v = sKV[(tx*4+1)*SV_STRIDE + kk];
            float k2v = sKV[(tx*4+2)*SV_STRIDE + kk];
            float k3v = sKV[(tx*4+3)*SV_STRIDE + kk];
            float q0 = sQ[(ty*4+0)*SQ_STRIDE + kk];
            float q1 = sQ[(ty*4+1)*SQ_STRIDE + kk];
            float q2 = sQ[(ty*4+2)*SQ_STRIDE + kk];
            float q3 = sQ[(ty*4+3)*SQ_STRIDE + kk];
            acc[0][0]+=q0*k0v; acc[0][1]+=q0*k1v; acc[0][2]+=q0*k2v; acc[0][3]+=q0*k3v;
            acc[1][0]+=q1*k0v; acc[1][1]+=q1*k1v; acc[1][2]+=q1*k2v; acc[1][3]+=q1*k3v;
            acc[2][0]+=q2*k0v; acc[2][1]+=q2*k1v; acc[2][2]+=q2*k2v; acc[2][3]+=q2*k3v;
            acc[3][0]+=q3*k0v; acc[3][1]+=q3*k1v; acc[3][2]+=q3*k2v; acc[3][3]+=q3*k3v;
        }
        const int jl = j0 + tx*4;
        #pragma unroll
        for (int r=0; r<4; ++r){
            int gi = i0 + ty*4 + r;
            float4 u4 = *(const float4*)(utT + ((long)b*S_ + gi)*S_ + jl);
            float4 w;
            w.x = acc[r][0]*kscale*u4.x;
            w.y = acc[r][1]*kscale*u4.y;
            w.z = acc[r][2]*kscale*u4.z;
            w.w = acc[r][3]*kscale*u4.w;
            *(float4*)(sS + (ty*4+r)*SS_STRIDE + jl) = w;
        }
    }
    __syncthreads();

    // ---- per-row softmax1 -> cumsum -> decay -> exp2 (unnormalized) ----
    {
        const int wid = tid >> 5, lane = tid & 31;   // 16 warps x 2 rows
        const unsigned FULL = 0xffffffffu;
        const float gh = -log1pf(__expf(gammas[h]));

        #pragma unroll 1
        for (int q=0; q<2; ++q){
            int r  = wid*2 + q;
            int gi = i0 + r;
            int L  = gi + 1;
            float* row = sS + r*SS_STRIDE;

            for (int j = L + lane; j < JMAX; j += 32) row[j] = 0.f;

            float mx = -1e30f;
            for (int j = lane; j < L; j += 32) mx = fmaxf(mx, row[j]);
            #pragma unroll
            for (int o=16;o>0;o>>=1) mx = fmaxf(mx, __shfl_xor_sync(FULL, mx, o));

            float sm = 0.f;
            for (int j = lane; j < L; j += 32) sm += __expf(row[j] - mx);
            #pragma unroll
            for (int o=16;o>0;o>>=1) sm += __shfl_xor_sync(FULL, sm, o);
            const float inv = 1.f / sm;

            float carry = 0.f, mx2 = -1e30f;
            int nch = (L + 31) >> 5;
            for (int c = 0; c < nch; ++c){
                int j = c*32 + lane;
                bool in = j < L;
                float s = in ? row[j] : 0.f;
                float e = in ? __expf(s - mx) : 0.f;
                float v = e;
                #pragma unroll
                for (int o=1;o<32;o<<=1){
                    float t = __shfl_up_sync(FULL, v, o);
                    if (lane >= o) v += t;
                }
                float cum = carry + v;
                carry += __shfl_sync(FULL, v, 31);
                if (in){
                    float rem = fmaxf(0.f, (sm - cum) * inv);
                    float pe  = fabsf((float)(gi - j));
                    float y   = rem * pe;
                    float dist = (y > 0.f) ? y * __frsqrt_rn(y) : 0.f;
                    float te = fmaxf(__expf(dist * gh), 1e-5f);
                    float s2 = s * te;
                    row[j] = s2;
                    mx2 = fmaxf(mx2, s2);
                }
            }
            #pragma unroll
            for (int o=16;o>0;o>>=1) mx2 = fmaxf(mx2, __shfl_xor_sync(FULL, mx2, o));

            float sm2 = 0.f;
            for (int j = lane; j < L; j += 32){
                float e2 = __expf(row[j] - mx2);
                row[j] = e2;
                sm2 += e2;
            }
            #pragma unroll
            for (int o=16;o>0;o>>=1) sm2 += __shfl_xor_sync(FULL, sm2, o);
            if (lane == 0) sInv[r] = 1.f / sm2;
        }
    }
    __syncthreads();

    // ---- out GEMM: out[i][d] = sInv[i] * sum_j e2[i][j] * v[j][d] ----
    {
        const int rg = tid >> 4;        // 32 rows
        const int dg = tid & 15;        // 16 x 4 d-cols
        float acc2[4] = {0.f,0.f,0.f,0.f};

        for (int jt=0; jt<TJn; ++jt){
            const int j0 = jt*BJ;
            __syncthreads();
            #pragma unroll
            for (int it=0; it<8; ++it){
                int idx = tid + it*512;
                int row = idx >> 4, c4 = (idx & 15)*4;
                float4 v = *(const float4*)(Vbase + (long)(j0+row)*DK_ + c4);
                *(float4*)(sKV + row*SV_STRIDE + c4) = v;
            }
            __syncthreads();
            const float* prow = sS + rg*SS_STRIDE + j0;
            #pragma unroll 4
            for (int jj=0; jj<BJ; ++jj){
                float p = prow[jj];
                float4 v4 = *(const float4*)(sKV + jj*SV_STRIDE + dg*4);
                acc2[0] += p*v4.x; acc2[1] += p*v4.y;
                acc2[2] += p*v4.z; acc2[3] += p*v4.w;
            }
        }

        float sc = sInv[rg];
        float4 w; w.x=acc2[0]*sc; w.y=acc2[1]*sc; w.z=acc2[2]*sc; w.w=acc2[3]*sc;
        *(float4*)(g_attn + ((long)b*S_ + i0 + rg)*D_ + h*DK_ + dg*4) = w;
    }
}

// ---------------------------------------------------------------------------
extern "C" void kernel_launch(void* const* d_in, const int* in_sizes, int n_in,
                              void* d_out, int out_size)
{
    const float* x      = (const float*)d_in[0];
    const float* utT    = (const float*)d_in[1];
    const float* Wk     = (const float*)d_in[2];
    const float* bk     = (const float*)d_in[3];
    const float* Wv     = (const float*)d_in[4];
    const float* bv     = (const float*)d_in[5];
    const float* Wo     = (const float*)d_in[6];
    const float* bo     = (const float*)d_in[7];
    const float* gammas = (const float*)d_in[8];
    float* out = (float*)d_out;

    float* qk; cudaGetSymbolAddress((void**)&qk, g_qk);
    float* vv; cudaGetSymbolAddress((void**)&vv, g_v);
    float* at; cudaGetSymbolAddress((void**)&at, g_attn);

    dim3 ggrid(D_/64, (B_*S_)/128);

    gemm128<<<ggrid, 256>>>(x, Wk, bk, qk, 1);
    gemm128<<<ggrid, 256>>>(x, Wv, bv, vv, 1);

    size_t smem_bytes = (size_t)(TM*SS_STRIDE + TM*SQ_STRIDE + BJ*SV_STRIDE + 32) * sizeof(float);
    cudaFuncSetAttribute(attn_kernel, cudaFuncAttributeMaxDynamicSharedMemorySize, (int)smem_bytes);
    attn_kernel<<<dim3(S_/TM, H_, B_), 512, smem_bytes>>>(utT, gammas);

    gemm128<<<ggrid, 256>>>(at, Wo, bo, out, 0);
}

// round 5
// speedup vs baseline: 1.6636x; 1.6636x over previous
#include <cuda_runtime.h>
#include <math.h>

#define B_ 8
#define S_ 1024
#define D_ 512
#define H_ 8
#define DK_ 64

#define TM 32
#define BJ 256
#define SS_STRIDE 1032
#define SQ_STRIDE 68
#define SKT_STRIDE 264
#define SV_STRIDE 68
#define KVBUF 17408   // max(64*264, 256*68)

// scratch (device globals; no allocation allowed)
__device__ float g_qk[B_*H_*S_*DK_];   // 16 MB, q == k (kq_same)
__device__ float g_v [B_*H_*S_*DK_];   // 16 MB
__device__ float g_attn[B_*S_*D_];     // 16 MB

// ---------------------------------------------------------------------------
// Kernel 1: fused QK / V projection (R1-proven, scalar FFMA at issue peak).
// 64x64 tiles, BK=16, 256 threads, 4x4 micro-tiles.  z selects Wk->g_qk or
// Wv->g_v, output head-split [b,h,s,dk].
// ---------------------------------------------------------------------------
__global__ __launch_bounds__(256) void proj_kernel(
    const float* __restrict__ x,
    const float* __restrict__ Wk, const float* __restrict__ bk,
    const float* __restrict__ Wv, const float* __restrict__ bv)
{
    __shared__ float sA[16*68];
    __shared__ float sB[16*68];

    const float* W    = blockIdx.z ? Wv : Wk;
    const float* bias = blockIdx.z ? bv : bk;
    float* dst        = blockIdx.z ? g_v : g_qk;

    const int m0 = blockIdx.y * 64;
    const int n0 = blockIdx.x * 64;
    const int tid = threadIdx.x;
    const int tx = tid & 15;
    const int ty = tid >> 4;
    const int lrow = tid >> 2;
    const int lc4  = tid & 3;

    float acc[4][4] = {};

    for (int k0 = 0; k0 < D_; k0 += 16) {
        float4 av = *(const float4*)(x + (long)(m0 + lrow)*D_ + k0 + lc4*4);
        float4 bw = *(const float4*)(W + (long)(n0 + lrow)*D_ + k0 + lc4*4);
        __syncthreads();
        sA[(lc4*4+0)*68 + lrow] = av.x;
        sA[(lc4*4+1)*68 + lrow] = av.y;
        sA[(lc4*4+2)*68 + lrow] = av.z;
        sA[(lc4*4+3)*68 + lrow] = av.w;
        sB[(lc4*4+0)*68 + lrow] = bw.x;
        sB[(lc4*4+1)*68 + lrow] = bw.y;
        sB[(lc4*4+2)*68 + lrow] = bw.z;
        sB[(lc4*4+3)*68 + lrow] = bw.w;
        __syncthreads();
        #pragma unroll
        for (int kk = 0; kk < 16; ++kk) {
            float4 a4 = *(const float4*)(sA + kk*68 + ty*4);
            float4 b4 = *(const float4*)(sB + kk*68 + tx*4);
            acc[0][0] += a4.x*b4.x; acc[0][1] += a4.x*b4.y; acc[0][2] += a4.x*b4.z; acc[0][3] += a4.x*b4.w;
            acc[1][0] += a4.y*b4.x; acc[1][1] += a4.y*b4.y; acc[1][2] += a4.y*b4.z; acc[1][3] += a4.y*b4.w;
            acc[2][0] += a4.z*b4.x; acc[2][1] += a4.z*b4.y; acc[2][2] += a4.z*b4.z; acc[2][3] += a4.z*b4.w;
            acc[3][0] += a4.w*b4.x; acc[3][1] += a4.w*b4.y; acc[3][2] += a4.w*b4.z; acc[3][3] += a4.w*b4.w;
        }
    }

    const int n = n0 + tx*4;
    const int hh = n >> 6;
    const int dd = n & 63;
    float4 bia = *(const float4*)(bias + n);
    #pragma unroll
    for (int r = 0; r < 4; ++r) {
        int m = m0 + ty*4 + r;
        int bb = m >> 10, ss = m & 1023;
        float4 v;
        v.x = acc[r][0] + bia.x;
        v.y = acc[r][1] + bia.y;
        v.z = acc[r][2] + bia.z;
        v.w = acc[r][3] + bia.w;
        *(float4*)(dst + (((long)bb*H_ + hh)*S_ + ss)*DK_ + dd) = v;
    }
}

// ---------------------------------------------------------------------------
// Kernel 2: attention with distance decay.  One block = 32 query rows of one
// (b,h), 512 threads.  Scores in SMEM; K transposed with XOR(k&60) swizzle.
// ---------------------------------------------------------------------------
__global__ __launch_bounds__(512) void attn_kernel(
    const float* __restrict__ utT, const float* __restrict__ gammas)
{
    extern __shared__ float smem[];
    float* sS   = smem;                       // 32*1032
    float* sQ   = sS  + TM*SS_STRIDE;         // 32*68
    float* sKV  = sQ  + TM*SQ_STRIDE;         // KVBUF (K^T or V tile)
    float* sInv = sKV + KVBUF;                // 32

    const int i0 = blockIdx.x * TM;
    const int h  = blockIdx.y;
    const int b  = blockIdx.z;
    const int tid = threadIdx.x;
    const long bh = (long)(b*H_ + h);
    const float* Kbase = g_qk + bh*(long)(S_*DK_);
    const float* Vbase = g_v  + bh*(long)(S_*DK_);
    const int TJn  = (i0 + TM + BJ - 1) / BJ;
    const int JMAX = TJn * BJ;

    // ---- load Q tile (32 x 64) ----
    {
        int row = tid >> 4, c4 = (tid & 15)*4;
        float4 v = *(const float4*)(Kbase + (long)(i0+row)*DK_ + c4);
        *(float4*)(sQ + row*SQ_STRIDE + c4) = v;
    }

    // ---- score GEMM: sS[i][j] = (q_i . k_j)/8 * utT[b,i,j] ----
    const int tx = tid & 63;    // 64 groups x 4 cols
    const int ty = tid >> 6;    // 8 groups x 4 rows
    const float kscale = 0.125f;

    for (int jt=0; jt<TJn; ++jt){
        const int j0 = jt*BJ;
        __syncthreads();
        // K^T with XOR swizzle: element k_j[k] stored at sKV[k*264 + (j ^ (k&60))]
        #pragma unroll
        for (int it=0; it<8; ++it){
            int idx = tid + it*512;        // 0..4095
            int jrow = idx >> 4;           // 0..255
            int c4   = (idx & 15)*4;       // 0..60 (mult of 4)
            float4 v = *(const float4*)(Kbase + (long)(j0+jrow)*DK_ + c4);
            int js = jrow ^ c4;            // (c4+i)&60 == c4 for i<4
            sKV[(c4+0)*SKT_STRIDE + js] = v.x;
            sKV[(c4+1)*SKT_STRIDE + js] = v.y;
            sKV[(c4+2)*SKT_STRIDE + js] = v.z;
            sKV[(c4+3)*SKT_STRIDE + js] = v.w;
        }
        __syncthreads();

        float acc[4][4] = {};
        #pragma unroll
        for (int kkc=0; kkc<16; ++kkc){
            const int cb = (tx*4) ^ (kkc*4);      // reads map back to j=tx*4+t
            const float* kb = sKV + (kkc*4)*SKT_STRIDE + cb;
            float4 k0 = *(const float4*)(kb);
            float4 k1 = *(const float4*)(kb + SKT_STRIDE);
            float4 k2 = *(const float4*)(kb + 2*SKT_STRIDE);
            float4 k3 = *(const float4*)(kb + 3*SKT_STRIDE);
            #pragma unroll
            for (int r=0; r<4; ++r){
                float4 q = *(const float4*)(sQ + (ty*4+r)*SQ_STRIDE + kkc*4);
                acc[r][0] += q.x*k0.x + q.y*k1.x + q.z*k2.x + q.w*k3.x;
                acc[r][1] += q.x*k0.y + q.y*k1.y + q.z*k2.y + q.w*k3.y;
                acc[r][2] += q.x*k0.z + q.y*k1.z + q.z*k2.z + q.w*k3.z;
                acc[r][3] += q.x*k0.w + q.y*k1.w + q.z*k2.w + q.w*k3.w;
            }
        }

        const int jl = j0 + tx*4;
        #pragma unroll
        for (int r=0; r<4; ++r){
            int gi = i0 + ty*4 + r;
            float4 u4 = *(const float4*)(utT + ((long)b*S_ + gi)*S_ + jl);
            float4 w;
            w.x = acc[r][0]*kscale*u4.x;
            w.y = acc[r][1]*kscale*u4.y;
            w.z = acc[r][2]*kscale*u4.z;
            w.w = acc[r][3]*kscale*u4.w;
            *(float4*)(sS + (ty*4+r)*SS_STRIDE + jl) = w;
        }
    }
    __syncthreads();

    // ---- per-row softmax1 -> cumsum -> decay -> exp2 (unnormalized) ----
    {
        const int wid = tid >> 5, lane = tid & 31;   // 16 warps x 2 rows
        const unsigned FULL = 0xffffffffu;
        const float gh = -log1pf(__expf(gammas[h]));

        #pragma unroll 1
        for (int q=0; q<2; ++q){
            int r  = wid*2 + q;
            int gi = i0 + r;
            int L  = gi + 1;
            float* row = sS + r*SS_STRIDE;

            for (int j = L + lane; j < JMAX; j += 32) row[j] = 0.f;

            float mx = -1e30f;
            for (int j = lane; j < L; j += 32) mx = fmaxf(mx, row[j]);
            #pragma unroll
            for (int o=16;o>0;o>>=1) mx = fmaxf(mx, __shfl_xor_sync(FULL, mx, o));

            float sm = 0.f;
            for (int j = lane; j < L; j += 32) sm += __expf(row[j] - mx);
            #pragma unroll
            for (int o=16;o>0;o>>=1) sm += __shfl_xor_sync(FULL, sm, o);
            const float inv = 1.f / sm;

            float carry = 0.f, mx2 = -1e30f;
            int nch = (L + 31) >> 5;
            for (int c = 0; c < nch; ++c){
                int j = c*32 + lane;
                bool in = j < L;
                float s = in ? row[j] : 0.f;
                float e = in ? __expf(s - mx) : 0.f;
                float v = e;
                #pragma unroll
                for (int o=1;o<32;o<<=1){
                    float t = __shfl_up_sync(FULL, v, o);
                    if (lane >= o) v += t;
                }
                float cum = carry + v;
                carry += __shfl_sync(FULL, v, 31);
                if (in){
                    float rem = fmaxf(0.f, (sm - cum) * inv);
                    float pe  = fabsf((float)(gi - j));
                    float y   = rem * pe;
                    float dist = (y > 0.f) ? y * __frsqrt_rn(y) : 0.f;
                    float te = fmaxf(__expf(dist * gh), 1e-5f);
                    float s2 = s * te;
                    row[j] = s2;
                    mx2 = fmaxf(mx2, s2);
                }
            }
            #pragma unroll
            for (int o=16;o>0;o>>=1) mx2 = fmaxf(mx2, __shfl_xor_sync(FULL, mx2, o));

            float sm2 = 0.f;
            for (int j = lane; j < L; j += 32){
                float e2 = __expf(row[j] - mx2);
                row[j] = e2;
                sm2 += e2;
            }
            #pragma unroll
            for (int o=16;o>0;o>>=1) sm2 += __shfl_xor_sync(FULL, sm2, o);
            if (lane == 0) sInv[r] = 1.f / sm2;
        }
    }

    // ---- out GEMM: out[i][d] = sInv[i] * sum_j e2[i][j] * v[j][d] ----
    {
        const int rg = tid >> 4;        // 32 rows
        const int dg = tid & 15;        // 16 x 4 d-cols
        float a0=0.f, a1=0.f, a2=0.f, a3=0.f;

        for (int jt=0; jt<TJn; ++jt){
            const int j0 = jt*BJ;
            __syncthreads();
            #pragma unroll
            for (int it=0; it<8; ++it){
                int idx = tid + it*512;
                int row = idx >> 4, c4 = (idx & 15)*4;
                float4 v = *(const float4*)(Vbase + (long)(j0+row)*DK_ + c4);
                *(float4*)(sKV + row*SV_STRIDE + c4) = v;
            }
            __syncthreads();
            const float* prow = sS + rg*SS_STRIDE + j0;
            #pragma unroll 2
            for (int jj=0; jj<BJ; jj+=4){
                float4 p4 = *(const float4*)(prow + jj);
                const float* vb = sKV + jj*SV_STRIDE + dg*4;
                float4 v0 = *(const float4*)(vb);
                float4 v1 = *(const float4*)(vb + SV_STRIDE);
                float4 v2 = *(const float4*)(vb + 2*SV_STRIDE);
                float4 v3 = *(const float4*)(vb + 3*SV_STRIDE);
                a0 += p4.x*v0.x + p4.y*v1.x + p4.z*v2.x + p4.w*v3.x;
                a1 += p4.x*v0.y + p4.y*v1.y + p4.z*v2.y + p4.w*v3.y;
                a2 += p4.x*v0.z + p4.y*v1.z + p4.z*v2.z + p4.w*v3.z;
                a3 += p4.x*v0.w + p4.y*v1.w + p4.z*v2.w + p4.w*v3.w;
            }
        }

        float sc = sInv[rg];
        float4 w; w.x=a0*sc; w.y=a1*sc; w.z=a2*sc; w.w=a3*sc;
        *(float4*)(g_attn + ((long)b*S_ + i0 + rg)*D_ + h*DK_ + dg*4) = w;
    }
}

// ---------------------------------------------------------------------------
// Kernel 3: output projection (R1-proven).  out = g_attn @ Wo^T + bo.
// ---------------------------------------------------------------------------
__global__ __launch_bounds__(256) void out_kernel(
    const float* __restrict__ Wo, const float* __restrict__ bo,
    float* __restrict__ out)
{
    __shared__ float sA[16*68];
    __shared__ float sB[16*68];

    const int m0 = blockIdx.y * 64;
    const int n0 = blockIdx.x * 64;
    const int tid = threadIdx.x;
    const int tx = tid & 15;
    const int ty = tid >> 4;
    const int lrow = tid >> 2;
    const int lc4  = tid & 3;

    float acc[4][4] = {};

    for (int k0 = 0; k0 < D_; k0 += 16) {
        float4 av = *(const float4*)(g_attn + (long)(m0 + lrow)*D_ + k0 + lc4*4);
        float4 bw = *(const float4*)(Wo     + (long)(n0 + lrow)*D_ + k0 + lc4*4);
        __syncthreads();
        sA[(lc4*4+0)*68 + lrow] = av.x;
        sA[(lc4*4+1)*68 + lrow] = av.y;
        sA[(lc4*4+2)*68 + lrow] = av.z;
        sA[(lc4*4+3)*68 + lrow] = av.w;
        sB[(lc4*4+0)*68 + lrow] = bw.x;
        sB[(lc4*4+1)*68 + lrow] = bw.y;
        sB[(lc4*4+2)*68 + lrow] = bw.z;
        sB[(lc4*4+3)*68 + lrow] = bw.w;
        __syncthreads();
        #pragma unroll
        for (int kk = 0; kk < 16; ++kk) {
            float4 a4 = *(const float4*)(sA + kk*68 + ty*4);
            float4 b4 = *(const float4*)(sB + kk*68 + tx*4);
            acc[0][0] += a4.x*b4.x; acc[0][1] += a4.x*b4.y; acc[0][2] += a4.x*b4.z; acc[0][3] += a4.x*b4.w;
            acc[1][0] += a4.y*b4.x; acc[1][1] += a4.y*b4.y; acc[1][2] += a4.y*b4.z; acc[1][3] += a4.y*b4.w;
            acc[2][0] += a4.z*b4.x; acc[2][1] += a4.z*b4.y; acc[2][2] += a4.z*b4.z; acc[2][3] += a4.z*b4.w;
            acc[3][0] += a4.w*b4.x; acc[3][1] += a4.w*b4.y; acc[3][2] += a4.w*b4.z; acc[3][3] += a4.w*b4.w;
        }
    }

    const int n = n0 + tx*4;
    float4 bia = *(const float4*)(bo + n);
    #pragma unroll
    for (int r = 0; r < 4; ++r) {
        int m = m0 + ty*4 + r;
        float4 v;
        v.x = acc[r][0] + bia.x;
        v.y = acc[r][1] + bia.y;
        v.z = acc[r][2] + bia.z;
        v.w = acc[r][3] + bia.w;
        *(float4*)(out + (long)m*D_ + n) = v;
    }
}

// ---------------------------------------------------------------------------
extern "C" void kernel_launch(void* const* d_in, const int* in_sizes, int n_in,
                              void* d_out, int out_size)
{
    const float* x      = (const float*)d_in[0];
    const float* utT    = (const float*)d_in[1];
    const float* Wk     = (const float*)d_in[2];
    const float* bk     = (const float*)d_in[3];
    const float* Wv     = (const float*)d_in[4];
    const float* bv     = (const float*)d_in[5];
    const float* Wo     = (const float*)d_in[6];
    const float* bo     = (const float*)d_in[7];
    const float* gammas = (const float*)d_in[8];
    float* out = (float*)d_out;

    // QK + V projections (z selects which weight)
    proj_kernel<<<dim3(D_/64, (B_*S_)/64, 2), 256>>>(x, Wk, bk, Wv, bv);

    // attention
    size_t smem_bytes = (size_t)(TM*SS_STRIDE + TM*SQ_STRIDE + KVBUF + 32) * sizeof(float);
    cudaFuncSetAttribute(attn_kernel, cudaFuncAttributeMaxDynamicSharedMemorySize, (int)smem_bytes);
    attn_kernel<<<dim3(S_/TM, H_, B_), 512, smem_bytes>>>(utT, gammas);

    // output projection
    out_kernel<<<dim3(D_/64, (B_*S_)/64), 256>>>(Wo, bo, out);
}